// round 4
// baseline (speedup 1.0000x reference)
#include <cuda_runtime.h>
#include <mma.h>
#include <cstdint>

using namespace nvcuda;

#define NN 50000
#define NE 1600000
#define DD 128
#define RR 24
#define BB 8
#define KB (BB*DD)   /* 1024 */

// ---------------- device scratch (static, allocation-free) ----------------
__device__ int   g_cnt_dst[NN];
__device__ int   g_row_ptr[NN+1];
__device__ int   g_cursor[NN];
__device__ int   g_cnt_nr[NN*RR];
__device__ float g_invc[NN*RR];
__device__ int   g_edges[NE];                 // src | (rel<<20)
__device__ float g_h0[(size_t)NN*DD];
__device__ float g_h1[(size_t)NN*DD];
__device__ float g_aggB[(size_t)NN*KB];       // ~205 MB

// ---------------- CSR build ----------------
__global__ void zero_counts_kernel(){
  int i = blockIdx.x*blockDim.x + threadIdx.x;
  const int tot = NN + NN*RR;
  if (i < tot){
    if (i < NN) g_cnt_dst[i] = 0; else g_cnt_nr[i-NN] = 0;
  }
}

__global__ void count_kernel(const int* __restrict__ ei, const int* __restrict__ et){
  int e = blockIdx.x*blockDim.x + threadIdx.x;
  if (e >= NE) return;
  int dst = ei[NE + e];
  int t   = et[e];
  atomicAdd(&g_cnt_dst[dst], 1);
  atomicAdd(&g_cnt_nr[dst*RR + t], 1);
}

__global__ void scan_kernel(){
  __shared__ int s[1024];
  int tid = threadIdx.x;
  int run = 0;
  if (tid == 0) g_row_ptr[0] = 0;
  for (int base = 0; base < NN; base += 1024){
    int idx = base + tid;
    int v = (idx < NN) ? g_cnt_dst[idx] : 0;
    s[tid] = v;
    __syncthreads();
    #pragma unroll
    for (int off = 1; off < 1024; off <<= 1){
      int a = (tid >= off) ? s[tid-off] : 0;
      __syncthreads();
      s[tid] += a;
      __syncthreads();
    }
    int incl = s[tid];
    if (idx < NN){
      g_row_ptr[idx+1] = run + incl;
      g_cursor[idx]    = run + incl - v;
    }
    run += s[1023];
    __syncthreads();
  }
}

__global__ void invc_kernel(){
  int i = blockIdx.x*blockDim.x + threadIdx.x;
  if (i < NN*RR){
    int c = g_cnt_nr[i];
    g_invc[i] = 1.0f / (float)(c > 1 ? c : 1);
  }
}

__global__ void scatter_kernel(const int* __restrict__ ei, const int* __restrict__ et){
  int e = blockIdx.x*blockDim.x + threadIdx.x;
  if (e >= NE) return;
  int src = ei[e];
  int dst = ei[NE + e];
  int t   = et[e];
  int pos = atomicAdd(&g_cursor[dst], 1);
  g_edges[pos] = src | (t << 20);
}

// ---------------- embedding gather ----------------
__global__ void embed_gather_kernel(const int* __restrict__ x, const float* __restrict__ emb){
  int i = blockIdx.x*blockDim.x + threadIdx.x;   // over NN*32 float4
  if (i >= NN*32) return;
  int n = i >> 5, c = i & 31;
  ((float4*)g_h0)[i] = ((const float4*)emb)[(size_t)x[n]*32 + c];
}

// ---------------- per-node aggregation -> aggB[n, b*128+i] ----------------
__global__ void __launch_bounds__(128) agg_kernel(int hsel, const float* __restrict__ comp){
  __shared__ float acc[RR*DD];      // 12 KB; column t is thread-private
  __shared__ float s_comp[RR*BB];
  __shared__ float s_inv[RR];
  const float* __restrict__ h = hsel ? g_h1 : g_h0;
  int n = blockIdx.x;
  int t = threadIdx.x;
  #pragma unroll
  for (int r = 0; r < RR; r++) acc[r*DD + t] = 0.f;
  for (int i = t; i < RR*BB; i += 128) s_comp[i] = comp[i];
  if (t < RR) s_inv[t] = g_invc[n*RR + t];
  __syncthreads();

  int e = g_row_ptr[n], end = g_row_ptr[n+1];
  for (; e + 4 <= end; e += 4){
    int p0 = __ldg(&g_edges[e+0]);
    int p1 = __ldg(&g_edges[e+1]);
    int p2 = __ldg(&g_edges[e+2]);
    int p3 = __ldg(&g_edges[e+3]);
    float v0 = __ldg(&h[(size_t)(p0 & 0xFFFFF)*DD + t]);
    float v1 = __ldg(&h[(size_t)(p1 & 0xFFFFF)*DD + t]);
    float v2 = __ldg(&h[(size_t)(p2 & 0xFFFFF)*DD + t]);
    float v3 = __ldg(&h[(size_t)(p3 & 0xFFFFF)*DD + t]);
    acc[(p0 >> 20)*DD + t] += v0;
    acc[(p1 >> 20)*DD + t] += v1;
    acc[(p2 >> 20)*DD + t] += v2;
    acc[(p3 >> 20)*DD + t] += v3;
  }
  for (; e < end; e++){
    int p = __ldg(&g_edges[e]);
    acc[(p >> 20)*DD + t] += __ldg(&h[(size_t)(p & 0xFFFFF)*DD + t]);
  }

  float ar[RR];
  #pragma unroll
  for (int r = 0; r < RR; r++) ar[r] = acc[r*DD + t] * s_inv[r];
  float* dst = &g_aggB[(size_t)n*KB];
  #pragma unroll
  for (int b = 0; b < BB; b++){
    float s = 0.f;
    #pragma unroll
    for (int r = 0; r < RR; r++) s += ar[r] * s_comp[r*BB + b];
    dst[b*DD + t] = s;
  }
}

// ---------------- fused GEMM: C = aggB@bases + h@root + bias (3xTF32) ----------------
__global__ void __launch_bounds__(256) gemm_kernel(
    int hsel,
    const float* __restrict__ B1,      // bases [1024,128] row-major
    const float* __restrict__ B2,      // root  [128,128]
    const float* __restrict__ bias,
    float* __restrict__ Cext,          // nullptr -> write g_h1
    int relu)
{
  constexpr int LDA_S = 24, LDB_S = 136;
  __shared__ __align__(32) float Ah[128*LDA_S];
  __shared__ __align__(32) float Al[128*LDA_S];
  __shared__ __align__(32) float Bh[16*LDB_S];
  __shared__ __align__(32) float Bl[16*LDB_S];
  __shared__ __align__(32) float s_bias[DD];

  const float* __restrict__ A2 = hsel ? g_h1 : g_h0;
  float* __restrict__ C = Cext ? Cext : g_h1;

  int tid = threadIdx.x;
  int wid = tid >> 5, lane = tid & 31;
  int wm = wid & 3, wn = wid >> 2;         // 4x2 warp grid, warp tile 32x64
  int m0 = blockIdx.x * 128;

  if (tid < DD) s_bias[tid] = bias[tid];

  wmma::fragment<wmma::accumulator,16,16,8,float> c[2][4];
  #pragma unroll
  for (int i = 0; i < 2; i++)
    #pragma unroll
    for (int j = 0; j < 4; j++) wmma::fill_fragment(c[i][j], 0.f);

  #pragma unroll
  for (int phase = 0; phase < 2; phase++){
    const float* __restrict__ A  = phase ? A2 : g_aggB;
    const float* __restrict__ Bm = phase ? B2 : B1;
    const int K = phase ? DD : KB;
    for (int k0 = 0; k0 < K; k0 += 16){
      // A tile: 128 rows x 16 cols  (512 float4, 2 per thread)
      #pragma unroll
      for (int u = 0; u < 2; u++){
        int idx = tid*2 + u;
        int rl = idx >> 2, c4 = idx & 3;
        int row = m0 + rl;
        float4 v = make_float4(0.f,0.f,0.f,0.f);
        if (row < NN) v = *(const float4*)(A + (size_t)row*K + k0 + c4*4);
        float* ph = &Ah[rl*LDA_S + c4*4];
        float* pl = &Al[rl*LDA_S + c4*4];
        float hx;
        hx = wmma::__float_to_tf32(v.x); ph[0]=hx; pl[0]=wmma::__float_to_tf32(v.x-hx);
        hx = wmma::__float_to_tf32(v.y); ph[1]=hx; pl[1]=wmma::__float_to_tf32(v.y-hx);
        hx = wmma::__float_to_tf32(v.z); ph[2]=hx; pl[2]=wmma::__float_to_tf32(v.z-hx);
        hx = wmma::__float_to_tf32(v.w); ph[3]=hx; pl[3]=wmma::__float_to_tf32(v.w-hx);
      }
      // B tile: 16 rows x 128 cols
      #pragma unroll
      for (int u = 0; u < 2; u++){
        int idx = tid*2 + u;
        int rl = idx >> 5, c4 = idx & 31;
        float4 v = *(const float4*)(Bm + (size_t)(k0+rl)*DD + c4*4);
        float* ph = &Bh[rl*LDB_S + c4*4];
        float* pl = &Bl[rl*LDB_S + c4*4];
        float hx;
        hx = wmma::__float_to_tf32(v.x); ph[0]=hx; pl[0]=wmma::__float_to_tf32(v.x-hx);
        hx = wmma::__float_to_tf32(v.y); ph[1]=hx; pl[1]=wmma::__float_to_tf32(v.y-hx);
        hx = wmma::__float_to_tf32(v.z); ph[2]=hx; pl[2]=wmma::__float_to_tf32(v.z-hx);
        hx = wmma::__float_to_tf32(v.w); ph[3]=hx; pl[3]=wmma::__float_to_tf32(v.w-hx);
      }
      __syncthreads();
      #pragma unroll
      for (int ks = 0; ks < 16; ks += 8){
        wmma::fragment<wmma::matrix_a,16,16,8,wmma::precision::tf32,wmma::row_major> ah[2], al[2];
        wmma::fragment<wmma::matrix_b,16,16,8,wmma::precision::tf32,wmma::row_major> bh[4], bl[4];
        #pragma unroll
        for (int i = 0; i < 2; i++){
          wmma::load_matrix_sync(ah[i], &Ah[(wm*32 + i*16)*LDA_S + ks], LDA_S);
          wmma::load_matrix_sync(al[i], &Al[(wm*32 + i*16)*LDA_S + ks], LDA_S);
        }
        #pragma unroll
        for (int j = 0; j < 4; j++){
          wmma::load_matrix_sync(bh[j], &Bh[ks*LDB_S + wn*64 + j*16], LDB_S);
          wmma::load_matrix_sync(bl[j], &Bl[ks*LDB_S + wn*64 + j*16], LDB_S);
        }
        #pragma unroll
        for (int i = 0; i < 2; i++)
          #pragma unroll
          for (int j = 0; j < 4; j++){
            wmma::mma_sync(c[i][j], ah[i], bh[j], c[i][j]);
            wmma::mma_sync(c[i][j], ah[i], bl[j], c[i][j]);
            wmma::mma_sync(c[i][j], al[i], bh[j], c[i][j]);
          }
      }
      __syncthreads();
    }
  }

  // ---- epilogue: stage each 16x16 tile through smem (ld=16, 32B-aligned) ----
  __syncthreads();                      // all mma smem reads done; safe to reuse Ah
  float* st = &Ah[wid*256];             // 256 floats (1 KB) per warp region
  int rr2  = lane >> 1;                 // 0..15 : row within tile
  int half = lane & 1;                  // 0/1   : which 8-col half
  #pragma unroll
  for (int i = 0; i < 2; i++)
    #pragma unroll
    for (int j = 0; j < 4; j++){
      wmma::store_matrix_sync(st, c[i][j], 16, wmma::mem_row_major);
      __syncwarp();
      int grow = m0 + wm*32 + i*16 + rr2;
      int gcol = wn*64 + j*16 + half*8;
      float4 v0 = *(const float4*)&st[rr2*16 + half*8];
      float4 v1 = *(const float4*)&st[rr2*16 + half*8 + 4];
      if (grow < NN){
        v0.x += s_bias[gcol+0]; v0.y += s_bias[gcol+1];
        v0.z += s_bias[gcol+2]; v0.w += s_bias[gcol+3];
        v1.x += s_bias[gcol+4]; v1.y += s_bias[gcol+5];
        v1.z += s_bias[gcol+6]; v1.w += s_bias[gcol+7];
        if (relu){
          v0.x = fmaxf(v0.x,0.f); v0.y = fmaxf(v0.y,0.f);
          v0.z = fmaxf(v0.z,0.f); v0.w = fmaxf(v0.w,0.f);
          v1.x = fmaxf(v1.x,0.f); v1.y = fmaxf(v1.y,0.f);
          v1.z = fmaxf(v1.z,0.f); v1.w = fmaxf(v1.w,0.f);
        }
        *(float4*)&C[(size_t)grow*DD + gcol]     = v0;
        *(float4*)&C[(size_t)grow*DD + gcol + 4] = v1;
      }
      __syncwarp();
    }
}

// ---------------- launch ----------------
extern "C" void kernel_launch(void* const* d_in, const int* in_sizes, int n_in,
                              void* d_out, int out_size) {
  const int*   x      = (const int*)  d_in[0];
  const int*   ei     = (const int*)  d_in[1];
  const int*   et     = (const int*)  d_in[2];
  const float* emb    = (const float*)d_in[3];
  const float* comp1  = (const float*)d_in[4];
  // bases1 = d_in[5], root1 = d_in[6], bias1 = d_in[7]
  const float* comp2  = (const float*)d_in[8];
  // bases2 = d_in[9], root2 = d_in[10], bias2 = d_in[11]
  float* out = (float*)d_out;

  const int T = 256;
  // CSR build (shared by both layers)
  zero_counts_kernel<<<(NN + NN*RR + T-1)/T, T>>>();
  count_kernel<<<(NE + T-1)/T, T>>>(ei, et);
  scan_kernel<<<1, 1024>>>();
  invc_kernel<<<(NN*RR + T-1)/T, T>>>();
  scatter_kernel<<<(NE + T-1)/T, T>>>(ei, et);

  // h0 = embed[x]
  embed_gather_kernel<<<(NN*32 + T-1)/T, T>>>(x, emb);

  const int GB = (NN + 127)/128;  // 391 gemm blocks

  // layer 1: aggB from h0, then h1 = relu(aggB@bases1 + h0@root1 + bias1)
  agg_kernel<<<NN, 128>>>(0, comp1);
  gemm_kernel<<<GB, 256>>>(0, (const float*)d_in[5], (const float*)d_in[6],
                           (const float*)d_in[7], nullptr, 1);

  // layer 2: aggB from h1, then out = aggB@bases2 + h1@root2 + bias2
  agg_kernel<<<NN, 128>>>(1, comp2);
  gemm_kernel<<<GB, 256>>>(1, (const float*)d_in[9], (const float*)d_in[10],
                           (const float*)d_in[11], out, 0);
}

// round 6
// speedup vs baseline: 1.2837x; 1.2837x over previous
#include <cuda_runtime.h>
#include <mma.h>
#include <cstdint>

using namespace nvcuda;

#define NN 50000
#define NE 1600000
#define DD 128
#define RR 24
#define BB 8
#define KB (BB*DD)   /* 1024 */

// ---------------- device scratch (static, allocation-free) ----------------
__device__ int   g_cnt_dst[NN];
__device__ int   g_row_ptr[NN+1];
__device__ int   g_cursor[NN];
__device__ int   g_cnt_nr[NN*RR];
__device__ int   g_edges[NE];                 // src | (rel<<20)
__device__ float g_h0[(size_t)NN*DD];
__device__ float g_h1[(size_t)NN*DD];
__device__ float g_aggB[(size_t)NN*KB];       // ~205 MB

// ---------------- launch 0: embedding gather + zero counters ----------------
__global__ void embed_zero_kernel(const int* __restrict__ x, const float* __restrict__ emb){
  int i = blockIdx.x*blockDim.x + threadIdx.x;   // grid covers NN*32 (>= NN*RR)
  if (i < NN*32){
    int n = i >> 5, c = i & 31;
    ((float4*)g_h0)[i] = ((const float4*)emb)[(size_t)x[n]*32 + c];
  }
  if (i < NN) g_cnt_dst[i] = 0;
  if (i < NN*RR) g_cnt_nr[i] = 0;
}

// ---------------- launch 1: degree histograms ----------------
__global__ void count_kernel(const int* __restrict__ ei, const int* __restrict__ et){
  int e = blockIdx.x*blockDim.x + threadIdx.x;
  if (e >= NE) return;
  int dst = ei[NE + e];
  int t   = et[e];
  atomicAdd(&g_cnt_dst[dst], 1);
  atomicAdd(&g_cnt_nr[dst*RR + t], 1);
}

// ---------------- launch 2: prefix scan (shuffle-based, 2 BAR/tile) ----------
__global__ void scan_kernel(){
  __shared__ int wsum[32], wpre[32], s_tot;
  int tid = threadIdx.x, lane = tid & 31, w = tid >> 5;
  int run = 0;
  if (tid == 0) g_row_ptr[0] = 0;
  for (int base = 0; base < NN; base += 1024){
    int idx = base + tid;
    int v = (idx < NN) ? g_cnt_dst[idx] : 0;
    int s = v;
    #pragma unroll
    for (int off = 1; off < 32; off <<= 1){
      int a = __shfl_up_sync(0xFFFFFFFF, s, off);
      if (lane >= off) s += a;
    }
    if (lane == 31) wsum[w] = s;
    __syncthreads();
    if (w == 0){
      int ws = wsum[lane];
      int t2 = ws;
      #pragma unroll
      for (int off = 1; off < 32; off <<= 1){
        int a = __shfl_up_sync(0xFFFFFFFF, t2, off);
        if (lane >= off) t2 += a;
      }
      wpre[lane] = t2 - ws;
      if (lane == 31) s_tot = t2;
    }
    __syncthreads();
    int incl = s + wpre[w];
    if (idx < NN){
      g_row_ptr[idx+1] = run + incl;
      g_cursor[idx]    = run + incl - v;
    }
    run += s_tot;
  }
}

// ---------------- launch 3: edge scatter into CSR ----------------
__global__ void scatter_kernel(const int* __restrict__ ei, const int* __restrict__ et){
  int e = blockIdx.x*blockDim.x + threadIdx.x;
  if (e >= NE) return;
  int src = ei[e];
  int dst = ei[NE + e];
  int t   = et[e];
  int pos = atomicAdd(&g_cursor[dst], 1);
  g_edges[pos] = src | (t << 20);
}

// ---------------- agg: per-node mean-by-relation -> aggB[n, b*128+i] -------
__global__ void __launch_bounds__(128) agg_kernel(int hsel, const float* __restrict__ comp){
  __shared__ float acc[RR*DD];      // 12 KB; column t thread-private -> no conflicts
  __shared__ float s_comp[RR*BB];
  __shared__ float s_inv[RR];
  const float* __restrict__ h = hsel ? g_h1 : g_h0;
  int n = blockIdx.x;
  int t = threadIdx.x;
  #pragma unroll
  for (int r = 0; r < RR; r++) acc[r*DD + t] = 0.f;
  for (int i = t; i < RR*BB; i += 128) s_comp[i] = comp[i];
  if (t < RR){
    int c = g_cnt_nr[n*RR + t];
    s_inv[t] = 1.0f / (float)(c > 1 ? c : 1);
  }
  __syncthreads();

  int e = g_row_ptr[n], end = g_row_ptr[n+1];
  for (; e + 8 <= end; e += 8){
    int p[8]; float v[8];
    #pragma unroll
    for (int u = 0; u < 8; u++) p[u] = __ldg(&g_edges[e+u]);
    #pragma unroll
    for (int u = 0; u < 8; u++) v[u] = __ldg(&h[(size_t)(p[u] & 0xFFFFF)*DD + t]);
    #pragma unroll
    for (int u = 0; u < 8; u++) acc[(p[u] >> 20)*DD + t] += v[u];
  }
  for (; e + 2 <= end; e += 2){
    int p0 = __ldg(&g_edges[e+0]);
    int p1 = __ldg(&g_edges[e+1]);
    float v0 = __ldg(&h[(size_t)(p0 & 0xFFFFF)*DD + t]);
    float v1 = __ldg(&h[(size_t)(p1 & 0xFFFFF)*DD + t]);
    acc[(p0 >> 20)*DD + t] += v0;
    acc[(p1 >> 20)*DD + t] += v1;
  }
  if (e < end){
    int p = __ldg(&g_edges[e]);
    acc[(p >> 20)*DD + t] += __ldg(&h[(size_t)(p & 0xFFFFF)*DD + t]);
  }

  float ar[RR];
  #pragma unroll
  for (int r = 0; r < RR; r++) ar[r] = acc[r*DD + t] * s_inv[r];
  float* dst = &g_aggB[(size_t)n*KB];
  #pragma unroll
  for (int b = 0; b < BB; b++){
    float s = 0.f;
    #pragma unroll
    for (int r = 0; r < RR; r++) s += ar[r] * s_comp[r*BB + b];
    dst[b*DD + t] = s;
  }
}

// ---------------- fused GEMM (3xTF32, register double-buffered) ------------
// C = aggB@bases + h@root + bias ; 72 flat k-chunks of 16 (64 aggB + 8 root)
__global__ void __launch_bounds__(256) gemm_kernel(
    int hsel,
    const float* __restrict__ B1,      // bases [1024,128] row-major
    const float* __restrict__ B2,      // root  [128,128]
    const float* __restrict__ bias,
    float* __restrict__ Cext,          // nullptr -> write g_h1
    int relu)
{
  constexpr int LDA_S = 24, LDB_S = 136;
  constexpr int NCHUNK = 72;
  __shared__ __align__(32) float Ah[128*LDA_S];
  __shared__ __align__(32) float Al[128*LDA_S];
  __shared__ __align__(32) float Bh[16*LDB_S];
  __shared__ __align__(32) float Bl[16*LDB_S];
  __shared__ __align__(32) float s_bias[DD];

  const float* __restrict__ A2 = hsel ? g_h1 : g_h0;
  float* __restrict__ C = Cext ? Cext : g_h1;

  int tid = threadIdx.x;
  int wid = tid >> 5, lane = tid & 31;
  int wm = wid & 3, wn = wid >> 2;         // 4x2 warp grid, warp tile 32x64
  int m0 = blockIdx.x * 128;

  if (tid < DD) s_bias[tid] = bias[tid];

  // per-thread load coordinates (2 float4 for A, 2 for B)
  const int rlA0 = (tid*2)   >> 2, c4A0 = (tid*2)   & 3;
  const int rlA1 = (tid*2+1) >> 2, c4A1 = (tid*2+1) & 3;
  const int rlB0 = (tid*2)   >> 5, cB0  = (tid*2)   & 31;
  const int rlB1 = (tid*2+1) >> 5, cB1  = (tid*2+1) & 31;

  auto fetch = [&](int chunk, float4& va0, float4& va1, float4& vb0, float4& vb1){
    va0 = va1 = vb0 = vb1 = make_float4(0.f,0.f,0.f,0.f);
    if (chunk >= NCHUNK) return;
    const float* A; const float* Bm; int K, k0;
    if (chunk < 64){ A = g_aggB; Bm = B1; K = KB; k0 = chunk*16; }
    else           { A = A2;     Bm = B2; K = DD; k0 = (chunk-64)*16; }
    int r0 = m0 + rlA0, r1 = m0 + rlA1;
    if (r0 < NN) va0 = *(const float4*)(A + (size_t)r0*K + k0 + c4A0*4);
    if (r1 < NN) va1 = *(const float4*)(A + (size_t)r1*K + k0 + c4A1*4);
    vb0 = *(const float4*)(Bm + (size_t)(k0+rlB0)*DD + cB0*4);
    vb1 = *(const float4*)(Bm + (size_t)(k0+rlB1)*DD + cB1*4);
  };

  auto cvt4 = [](float4 v, float* ph, float* pl){
    float hx;
    hx = wmma::__float_to_tf32(v.x); ph[0]=hx; pl[0]=wmma::__float_to_tf32(v.x-hx);
    hx = wmma::__float_to_tf32(v.y); ph[1]=hx; pl[1]=wmma::__float_to_tf32(v.y-hx);
    hx = wmma::__float_to_tf32(v.z); ph[2]=hx; pl[2]=wmma::__float_to_tf32(v.z-hx);
    hx = wmma::__float_to_tf32(v.w); ph[3]=hx; pl[3]=wmma::__float_to_tf32(v.w-hx);
  };

  wmma::fragment<wmma::accumulator,16,16,8,float> c[2][4];
  #pragma unroll
  for (int i = 0; i < 2; i++)
    #pragma unroll
    for (int j = 0; j < 4; j++) wmma::fill_fragment(c[i][j], 0.f);

  float4 a0,a1,b0,b1, na0,na1,nb0,nb1;
  fetch(0, a0,a1,b0,b1);

  for (int chunk = 0; chunk < NCHUNK; chunk++){
    // stage current chunk (regs -> split tf32 smem)
    cvt4(a0, &Ah[rlA0*LDA_S + c4A0*4], &Al[rlA0*LDA_S + c4A0*4]);
    cvt4(a1, &Ah[rlA1*LDA_S + c4A1*4], &Al[rlA1*LDA_S + c4A1*4]);
    cvt4(b0, &Bh[rlB0*LDB_S + cB0*4],  &Bl[rlB0*LDB_S + cB0*4]);
    cvt4(b1, &Bh[rlB1*LDB_S + cB1*4],  &Bl[rlB1*LDB_S + cB1*4]);
    __syncthreads();

    // issue next chunk's global loads (in flight during mma)
    fetch(chunk+1, na0,na1,nb0,nb1);

    #pragma unroll
    for (int ks = 0; ks < 16; ks += 8){
      wmma::fragment<wmma::matrix_a,16,16,8,wmma::precision::tf32,wmma::row_major> ah[2], al[2];
      wmma::fragment<wmma::matrix_b,16,16,8,wmma::precision::tf32,wmma::row_major> bh[4], bl[4];
      #pragma unroll
      for (int i = 0; i < 2; i++){
        wmma::load_matrix_sync(ah[i], &Ah[(wm*32 + i*16)*LDA_S + ks], LDA_S);
        wmma::load_matrix_sync(al[i], &Al[(wm*32 + i*16)*LDA_S + ks], LDA_S);
      }
      #pragma unroll
      for (int j = 0; j < 4; j++){
        wmma::load_matrix_sync(bh[j], &Bh[ks*LDB_S + wn*64 + j*16], LDB_S);
        wmma::load_matrix_sync(bl[j], &Bl[ks*LDB_S + wn*64 + j*16], LDB_S);
      }
      #pragma unroll
      for (int i = 0; i < 2; i++)
        #pragma unroll
        for (int j = 0; j < 4; j++){
          wmma::mma_sync(c[i][j], ah[i], bh[j], c[i][j]);
          wmma::mma_sync(c[i][j], ah[i], bl[j], c[i][j]);
          wmma::mma_sync(c[i][j], al[i], bh[j], c[i][j]);
        }
    }
    __syncthreads();
    a0=na0; a1=na1; b0=nb0; b1=nb1;
  }

  // ---- epilogue: stage each 16x16 tile through smem (ld=16, 32B-aligned) ----
  float* st = &Ah[wid*256];             // 256 floats (1 KB) per warp region
  int rr2  = lane >> 1;                 // 0..15 : row within tile
  int half = lane & 1;                  // 0/1   : which 8-col half
  #pragma unroll
  for (int i = 0; i < 2; i++)
    #pragma unroll
    for (int j = 0; j < 4; j++){
      wmma::store_matrix_sync(st, c[i][j], 16, wmma::mem_row_major);
      __syncwarp();
      int grow = m0 + wm*32 + i*16 + rr2;
      int gcol = wn*64 + j*16 + half*8;
      float4 v0 = *(const float4*)&st[rr2*16 + half*8];
      float4 v1 = *(const float4*)&st[rr2*16 + half*8 + 4];
      if (grow < NN){
        v0.x += s_bias[gcol+0]; v0.y += s_bias[gcol+1];
        v0.z += s_bias[gcol+2]; v0.w += s_bias[gcol+3];
        v1.x += s_bias[gcol+4]; v1.y += s_bias[gcol+5];
        v1.z += s_bias[gcol+6]; v1.w += s_bias[gcol+7];
        if (relu){
          v0.x = fmaxf(v0.x,0.f); v0.y = fmaxf(v0.y,0.f);
          v0.z = fmaxf(v0.z,0.f); v0.w = fmaxf(v0.w,0.f);
          v1.x = fmaxf(v1.x,0.f); v1.y = fmaxf(v1.y,0.f);
          v1.z = fmaxf(v1.z,0.f); v1.w = fmaxf(v1.w,0.f);
        }
        *(float4*)&C[(size_t)grow*DD + gcol]     = v0;
        *(float4*)&C[(size_t)grow*DD + gcol + 4] = v1;
      }
      __syncwarp();
    }
}

// ---------------- launch ----------------
extern "C" void kernel_launch(void* const* d_in, const int* in_sizes, int n_in,
                              void* d_out, int out_size) {
  const int*   x      = (const int*)  d_in[0];
  const int*   ei     = (const int*)  d_in[1];
  const int*   et     = (const int*)  d_in[2];
  const float* emb    = (const float*)d_in[3];
  const float* comp1  = (const float*)d_in[4];
  const float* comp2  = (const float*)d_in[8];
  float* out = (float*)d_out;

  const int T = 256;
  embed_zero_kernel<<<(NN*32 + T-1)/T, T>>>(x, emb);          // 0
  count_kernel<<<(NE + T-1)/T, T>>>(ei, et);                   // 1
  scan_kernel<<<1, 1024>>>();                                  // 2
  scatter_kernel<<<(NE + T-1)/T, T>>>(ei, et);                 // 3

  const int GB = (NN + 127)/128;  // 391 gemm blocks

  agg_kernel<<<NN, 128>>>(0, comp1);                           // 4
  gemm_kernel<<<GB, 256>>>(0, (const float*)d_in[5], (const float*)d_in[6],
                           (const float*)d_in[7], nullptr, 1); // 5
  agg_kernel<<<NN, 128>>>(1, comp2);                           // 6
  gemm_kernel<<<GB, 256>>>(1, (const float*)d_in[9], (const float*)d_in[10],
                           (const float*)d_in[11], out, 0);    // 7
}

// round 8
// speedup vs baseline: 1.3016x; 1.0140x over previous
#include <cuda_runtime.h>
#include <mma.h>
#include <cstdint>

using namespace nvcuda;

#define NN 50000
#define NE 1600000
#define DD 128
#define RR 24
#define BB 8
#define KB (BB*DD)   /* 1024 */

// ---------------- device scratch (static, allocation-free) ----------------
// NOTE: g_cnt_dst / g_cnt_nr are zero on entry to every kernel_launch call:
// CUDA zero-initializes __device__ globals at module load, and the tail of the
// final gemm launch re-zeros them for the next call/replay. Deterministic.
__device__ int   g_cnt_dst[NN];
__device__ int   g_row_ptr[NN+1];
__device__ int   g_cursor[NN];
__device__ int   g_cnt_nr[NN*RR];
__device__ int   g_edges[NE];                 // src | (rel<<20)
__device__ float g_h0[(size_t)NN*DD];
__device__ float g_h1[(size_t)NN*DD];
__device__ float g_aggB[(size_t)NN*KB];       // ~205 MB

// ---------------- launch 0: embedding gather + degree histograms -----------
// grid covers NE = NN*32 threads exactly.
__global__ void embed_count_kernel(const int* __restrict__ x, const float* __restrict__ emb,
                                   const int* __restrict__ ei, const int* __restrict__ et){
  int i = blockIdx.x*blockDim.x + threadIdx.x;
  if (i < NN*32){
    int n = i >> 5, c = i & 31;
    ((float4*)g_h0)[i] = ((const float4*)emb)[(size_t)x[n]*32 + c];
  }
  if (i < NE){
    int dst = ei[NE + i];
    int t   = et[i];
    atomicAdd(&g_cnt_dst[dst], 1);
    atomicAdd(&g_cnt_nr[dst*RR + t], 1);
  }
}

// ---------------- launch 1: prefix scan (shuffle-based, 2 BAR/tile) --------
__global__ void scan_kernel(){
  __shared__ int wsum[32], wpre[32], s_tot;
  int tid = threadIdx.x, lane = tid & 31, w = tid >> 5;
  int run = 0;
  if (tid == 0) g_row_ptr[0] = 0;
  for (int base = 0; base < NN; base += 1024){
    int idx = base + tid;
    int v = (idx < NN) ? g_cnt_dst[idx] : 0;
    int s = v;
    #pragma unroll
    for (int off = 1; off < 32; off <<= 1){
      int a = __shfl_up_sync(0xFFFFFFFF, s, off);
      if (lane >= off) s += a;
    }
    if (lane == 31) wsum[w] = s;
    __syncthreads();
    if (w == 0){
      int ws = wsum[lane];
      int t2 = ws;
      #pragma unroll
      for (int off = 1; off < 32; off <<= 1){
        int a = __shfl_up_sync(0xFFFFFFFF, t2, off);
        if (lane >= off) t2 += a;
      }
      wpre[lane] = t2 - ws;
      if (lane == 31) s_tot = t2;
    }
    __syncthreads();
    int incl = s + wpre[w];
    if (idx < NN){
      g_row_ptr[idx+1] = run + incl;
      g_cursor[idx]    = run + incl - v;
    }
    run += s_tot;
  }
}

// ---------------- launch 2: edge scatter into CSR ----------------
__global__ void scatter_kernel(const int* __restrict__ ei, const int* __restrict__ et){
  int e = blockIdx.x*blockDim.x + threadIdx.x;
  if (e >= NE) return;
  int src = ei[e];
  int dst = ei[NE + e];
  int t   = et[e];
  int pos = atomicAdd(&g_cursor[dst], 1);
  g_edges[pos] = src | (t << 20);
}

// ---------------- agg: warp-per-node, register accumulators ----------------
// aggB[n, b*128+c] = sum_edges invc(n,rel)*comp[rel,b]*h[src,c]
// (identical math to mean-per-relation then basis-fold; weights distribute)
__global__ void __launch_bounds__(256, 3) agg_kernel(int hsel, const float* __restrict__ comp){
  __shared__ __align__(16) float s_w[8][RR*BB];   // per-warp weight table (6 KB)
  const float* __restrict__ h = hsel ? g_h1 : g_h0;
  int w = threadIdx.x >> 5, lane = threadIdx.x & 31;
  int n = blockIdx.x*8 + w;                        // grid = NN/8 exactly
  if (n >= NN) return;

  // build per-node weight table: wt[r*8+b] = comp[r*8+b] / max(cnt(n,r),1)
  float* wt = s_w[w];
  for (int i = lane; i < RR*BB; i += 32){
    int r = i >> 3;
    int c = g_cnt_nr[n*RR + r];
    wt[i] = comp[i] / (float)(c > 1 ? c : 1);
  }
  __syncwarp();

  float4 acc[BB];
  #pragma unroll
  for (int b = 0; b < BB; b++) acc[b] = make_float4(0.f,0.f,0.f,0.f);

  int e = g_row_ptr[n], end = g_row_ptr[n+1];

  #define ACC_EDGE(V, P) { \
    const float* wr = wt + ((P) >> 20)*BB; \
    float4 w0 = *(const float4*)wr; \
    float4 w1 = *(const float4*)(wr+4); \
    acc[0].x += w0.x*(V).x; acc[0].y += w0.x*(V).y; acc[0].z += w0.x*(V).z; acc[0].w += w0.x*(V).w; \
    acc[1].x += w0.y*(V).x; acc[1].y += w0.y*(V).y; acc[1].z += w0.y*(V).z; acc[1].w += w0.y*(V).w; \
    acc[2].x += w0.z*(V).x; acc[2].y += w0.z*(V).y; acc[2].z += w0.z*(V).z; acc[2].w += w0.z*(V).w; \
    acc[3].x += w0.w*(V).x; acc[3].y += w0.w*(V).y; acc[3].z += w0.w*(V).z; acc[3].w += w0.w*(V).w; \
    acc[4].x += w1.x*(V).x; acc[4].y += w1.x*(V).y; acc[4].z += w1.x*(V).z; acc[4].w += w1.x*(V).w; \
    acc[5].x += w1.y*(V).x; acc[5].y += w1.y*(V).y; acc[5].z += w1.y*(V).z; acc[5].w += w1.y*(V).w; \
    acc[6].x += w1.z*(V).x; acc[6].y += w1.z*(V).y; acc[6].z += w1.z*(V).z; acc[6].w += w1.z*(V).w; \
    acc[7].x += w1.w*(V).x; acc[7].y += w1.w*(V).y; acc[7].z += w1.w*(V).z; acc[7].w += w1.w*(V).w; }

  for (; e + 4 <= end; e += 4){
    int p0 = g_edges[e+0], p1 = g_edges[e+1], p2 = g_edges[e+2], p3 = g_edges[e+3];
    float4 v0 = *(const float4*)&h[(size_t)(p0 & 0xFFFFF)*DD + lane*4];
    float4 v1 = *(const float4*)&h[(size_t)(p1 & 0xFFFFF)*DD + lane*4];
    float4 v2 = *(const float4*)&h[(size_t)(p2 & 0xFFFFF)*DD + lane*4];
    float4 v3 = *(const float4*)&h[(size_t)(p3 & 0xFFFFF)*DD + lane*4];
    ACC_EDGE(v0, p0); ACC_EDGE(v1, p1); ACC_EDGE(v2, p2); ACC_EDGE(v3, p3);
  }
  for (; e < end; e++){
    int p = g_edges[e];
    float4 v = *(const float4*)&h[(size_t)(p & 0xFFFFF)*DD + lane*4];
    ACC_EDGE(v, p);
  }
  #undef ACC_EDGE

  float* dst = &g_aggB[(size_t)n*KB];
  #pragma unroll
  for (int b = 0; b < BB; b++)
    *(float4*)&dst[b*DD + lane*4] = acc[b];
}

// ---------------- fused GEMM (3xTF32, register double-buffered) ------------
// C = aggB@bases + h@root + bias ; 72 flat k-chunks of 16 (64 aggB + 8 root)
__global__ void __launch_bounds__(256) gemm_kernel(
    int hsel,
    const float* __restrict__ B1,      // bases [1024,128] row-major
    const float* __restrict__ B2,      // root  [128,128]
    const float* __restrict__ bias,
    float* __restrict__ Cext,          // nullptr -> write g_h1
    int relu,
    int zero_counters)                 // last launch: reset histograms for next call
{
  constexpr int LDA_S = 24, LDB_S = 136;
  constexpr int NCHUNK = 72;
  __shared__ __align__(32) float Ah[128*LDA_S];
  __shared__ __align__(32) float Al[128*LDA_S];
  __shared__ __align__(32) float Bh[16*LDB_S];
  __shared__ __align__(32) float Bl[16*LDB_S];
  __shared__ __align__(32) float s_bias[DD];

  const float* __restrict__ A2 = hsel ? g_h1 : g_h0;
  float* __restrict__ C = Cext ? Cext : g_h1;

  int tid = threadIdx.x;
  int wid = tid >> 5, lane = tid & 31;
  int wm = wid & 3, wn = wid >> 2;         // 4x2 warp grid, warp tile 32x64
  int m0 = blockIdx.x * 128;

  if (tid < DD) s_bias[tid] = bias[tid];

  const int rlA0 = (tid*2)   >> 2, c4A0 = (tid*2)   & 3;
  const int rlA1 = (tid*2+1) >> 2, c4A1 = (tid*2+1) & 3;
  const int rlB0 = (tid*2)   >> 5, cB0  = (tid*2)   & 31;
  const int rlB1 = (tid*2+1) >> 5, cB1  = (tid*2+1) & 31;

  auto fetch = [&](int chunk, float4& va0, float4& va1, float4& vb0, float4& vb1){
    va0 = va1 = vb0 = vb1 = make_float4(0.f,0.f,0.f,0.f);
    if (chunk >= NCHUNK) return;
    const float* A; const float* Bm; int K, k0;
    if (chunk < 64){ A = g_aggB; Bm = B1; K = KB; k0 = chunk*16; }
    else           { A = A2;     Bm = B2; K = DD; k0 = (chunk-64)*16; }
    int r0 = m0 + rlA0, r1 = m0 + rlA1;
    if (r0 < NN) va0 = *(const float4*)(A + (size_t)r0*K + k0 + c4A0*4);
    if (r1 < NN) va1 = *(const float4*)(A + (size_t)r1*K + k0 + c4A1*4);
    vb0 = *(const float4*)(Bm + (size_t)(k0+rlB0)*DD + cB0*4);
    vb1 = *(const float4*)(Bm + (size_t)(k0+rlB1)*DD + cB1*4);
  };

  auto cvt4 = [](float4 v, float* ph, float* pl){
    float hx;
    hx = wmma::__float_to_tf32(v.x); ph[0]=hx; pl[0]=wmma::__float_to_tf32(v.x-hx);
    hx = wmma::__float_to_tf32(v.y); ph[1]=hx; pl[1]=wmma::__float_to_tf32(v.y-hx);
    hx = wmma::__float_to_tf32(v.z); ph[2]=hx; pl[2]=wmma::__float_to_tf32(v.z-hx);
    hx = wmma::__float_to_tf32(v.w); ph[3]=hx; pl[3]=wmma::__float_to_tf32(v.w-hx);
  };

  wmma::fragment<wmma::accumulator,16,16,8,float> c[2][4];
  #pragma unroll
  for (int i = 0; i < 2; i++)
    #pragma unroll
    for (int j = 0; j < 4; j++) wmma::fill_fragment(c[i][j], 0.f);

  float4 a0,a1,b0,b1, na0,na1,nb0,nb1;
  fetch(0, a0,a1,b0,b1);

  for (int chunk = 0; chunk < NCHUNK; chunk++){
    // issue next chunk's global loads FIRST (independent of staging regs)
    fetch(chunk+1, na0,na1,nb0,nb1);

    // stage current chunk (regs -> split tf32 smem)
    cvt4(a0, &Ah[rlA0*LDA_S + c4A0*4], &Al[rlA0*LDA_S + c4A0*4]);
    cvt4(a1, &Ah[rlA1*LDA_S + c4A1*4], &Al[rlA1*LDA_S + c4A1*4]);
    cvt4(b0, &Bh[rlB0*LDB_S + cB0*4],  &Bl[rlB0*LDB_S + cB0*4]);
    cvt4(b1, &Bh[rlB1*LDB_S + cB1*4],  &Bl[rlB1*LDB_S + cB1*4]);
    __syncthreads();

    #pragma unroll
    for (int ks = 0; ks < 16; ks += 8){
      wmma::fragment<wmma::matrix_a,16,16,8,wmma::precision::tf32,wmma::row_major> ah[2], al[2];
      wmma::fragment<wmma::matrix_b,16,16,8,wmma::precision::tf32,wmma::row_major> bh[4], bl[4];
      #pragma unroll
      for (int i = 0; i < 2; i++){
        wmma::load_matrix_sync(ah[i], &Ah[(wm*32 + i*16)*LDA_S + ks], LDA_S);
        wmma::load_matrix_sync(al[i], &Al[(wm*32 + i*16)*LDA_S + ks], LDA_S);
      }
      #pragma unroll
      for (int j = 0; j < 4; j++){
        wmma::load_matrix_sync(bh[j], &Bh[ks*LDB_S + wn*64 + j*16], LDB_S);
        wmma::load_matrix_sync(bl[j], &Bl[ks*LDB_S + wn*64 + j*16], LDB_S);
      }
      #pragma unroll
      for (int i = 0; i < 2; i++)
        #pragma unroll
        for (int j = 0; j < 4; j++){
          wmma::mma_sync(c[i][j], ah[i], bh[j], c[i][j]);
          wmma::mma_sync(c[i][j], ah[i], bl[j], c[i][j]);
          wmma::mma_sync(c[i][j], al[i], bh[j], c[i][j]);
        }
    }
    __syncthreads();
    a0=na0; a1=na1; b0=nb0; b1=nb1;
  }

  // ---- epilogue: stage each 16x16 tile through smem (ld=16, 32B-aligned) ----
  float* st = &Ah[wid*256];
  int rr2  = lane >> 1;
  int half = lane & 1;
  #pragma unroll
  for (int i = 0; i < 2; i++)
    #pragma unroll
    for (int j = 0; j < 4; j++){
      wmma::store_matrix_sync(st, c[i][j], 16, wmma::mem_row_major);
      __syncwarp();
      int grow = m0 + wm*32 + i*16 + rr2;
      int gcol = wn*64 + j*16 + half*8;
      float4 v0 = *(const float4*)&st[rr2*16 + half*8];
      float4 v1 = *(const float4*)&st[rr2*16 + half*8 + 4];
      if (grow < NN){
        v0.x += s_bias[gcol+0]; v0.y += s_bias[gcol+1];
        v0.z += s_bias[gcol+2]; v0.w += s_bias[gcol+3];
        v1.x += s_bias[gcol+4]; v1.y += s_bias[gcol+5];
        v1.z += s_bias[gcol+6]; v1.w += s_bias[gcol+7];
        if (relu){
          v0.x = fmaxf(v0.x,0.f); v0.y = fmaxf(v0.y,0.f);
          v0.z = fmaxf(v0.z,0.f); v0.w = fmaxf(v0.w,0.f);
          v1.x = fmaxf(v1.x,0.f); v1.y = fmaxf(v1.y,0.f);
          v1.z = fmaxf(v1.z,0.f); v1.w = fmaxf(v1.w,0.f);
        }
        *(float4*)&C[(size_t)grow*DD + gcol]     = v0;
        *(float4*)&C[(size_t)grow*DD + gcol + 4] = v1;
      }
      __syncwarp();
    }

  // ---- tail of final launch: reset histograms for the next call/replay ----
  if (zero_counters){
    int gsz = gridDim.x * blockDim.x;
    int gi  = blockIdx.x * blockDim.x + tid;
    for (int i = gi; i < NN + NN*RR; i += gsz){
      if (i < NN) g_cnt_dst[i] = 0; else g_cnt_nr[i-NN] = 0;
    }
  }
}

// ---------------- launch ----------------
extern "C" void kernel_launch(void* const* d_in, const int* in_sizes, int n_in,
                              void* d_out, int out_size) {
  const int*   x      = (const int*)  d_in[0];
  const int*   ei     = (const int*)  d_in[1];
  const int*   et     = (const int*)  d_in[2];
  const float* emb    = (const float*)d_in[3];
  const float* comp1  = (const float*)d_in[4];
  const float* comp2  = (const float*)d_in[8];
  float* out = (float*)d_out;

  const int T = 256;
  embed_count_kernel<<<(NE + T-1)/T, T>>>(x, emb, ei, et);     // 0
  scan_kernel<<<1, 1024>>>();                                  // 1
  scatter_kernel<<<(NE + T-1)/T, T>>>(ei, et);                 // 2

  const int GB = (NN + 127)/128;  // 391 gemm blocks

  agg_kernel<<<NN/8, 256>>>(0, comp1);                         // 3  <- profiled
  gemm_kernel<<<GB, 256>>>(0, (const float*)d_in[5], (const float*)d_in[6],
                           (const float*)d_in[7], nullptr, 1, 0);  // 4
  agg_kernel<<<NN/8, 256>>>(1, comp2);                         // 5
  gemm_kernel<<<GB, 256>>>(1, (const float*)d_in[9], (const float*)d_in[10],
                           (const float*)d_in[11], out, 0, 1); // 6
}